// round 2
// baseline (speedup 1.0000x reference)
#include <cuda_runtime.h>
#include <math.h>
#include <stdint.h>

#define BB 2
#define SS 1024
#define DD 768
#define DINNER 1536
#define NH 24
#define HD 64
#define DS 64
#define DMLP 1920
#define PROJ 6936
#define NTOK (BB*SS)

// ---------------- scratch (device globals; no allocations allowed) ----------------
__device__ __align__(16) float g_h   [NTOK*DD];
__device__ __align__(16) float g_proj[NTOK*PROJ];
__device__ __align__(16) float g_Bm  [NTOK*NH*DS];
__device__ __align__(16) float g_Cm  [NTOK*NH*DS];
__device__ __align__(16) float g_dth [NTOK*NH*(DS/2)];
__device__ __align__(16) float g_alpha[NTOK*NH];
__device__ __align__(16) float g_gamma[NTOK*NH];
__device__ __align__(16) float g_sumx [NTOK*NH];
__device__ __align__(16) float g_y   [NTOK*DINNER];
__device__ __align__(16) float g_x2  [NTOK*DD];
__device__ __align__(16) float g_h2  [NTOK*DD];
__device__ __align__(16) float g_g   [NTOK*DMLP];
__device__ __align__(16) float g_u   [NTOK*DMLP];

__device__ __forceinline__ float* resolve(int id) {
    switch (id) {
        case 1: return g_h;
        case 2: return g_proj;
        case 3: return g_y;
        case 4: return g_x2;
        case 5: return g_h2;
        case 6: return g_g;
        case 7: return g_u;
    }
    return nullptr;
}

// ---------------- rmsnorm (row of 768) ----------------
__global__ void rmsnorm_kernel(const float* __restrict__ src_ext, int src_id,
                               int dst_id, const float* __restrict__ w) {
    const float* src = src_ext ? src_ext : resolve(src_id);
    float* dst = resolve(dst_id);
    int t = blockIdx.x;
    const float* row = src + (size_t)t * DD;
    float s = 0.f;
    for (int i = threadIdx.x; i < DD; i += blockDim.x) { float v = row[i]; s += v * v; }
    __shared__ float sh[8];
    for (int o = 16; o; o >>= 1) s += __shfl_down_sync(0xffffffffu, s, o);
    if ((threadIdx.x & 31) == 0) sh[threadIdx.x >> 5] = s;
    __syncthreads();
    if (threadIdx.x < 8) {
        float v = sh[threadIdx.x];
        for (int o = 4; o; o >>= 1) v += __shfl_down_sync(0xffu, v, o);
        if (threadIdx.x == 0) sh[0] = v;
    }
    __syncthreads();
    float scale = rsqrtf(sh[0] / (float)DD + 1e-5f);
    float* drow = dst + (size_t)t * DD;
    for (int i = threadIdx.x; i < DD; i += blockDim.x) drow[i] = row[i] * scale * w[i];
}

// ---------------- tiled fp32 NT GEMM: C[M,N] = A[M,K] * W[N,K]^T (+R) -------------
// BM=128, BN=64, BK=16, 256 threads, 8x4 per thread.
__global__ __launch_bounds__(256)
void gemm_nt(const float* __restrict__ A_ext, int A_id,
             const float* __restrict__ W,
             const float* __restrict__ R_ext, int R_id,
             float* __restrict__ C_ext, int C_id,
             int M, int N, int K, int epi) {
    const float* A = A_ext ? A_ext : resolve(A_id);
    float* C = C_ext ? C_ext : resolve(C_id);
    const float* R = (epi == 1) ? (R_ext ? R_ext : resolve(R_id)) : nullptr;

    __shared__ float As[16][128];
    __shared__ float Ws[16][64];

    int tid = threadIdx.x;
    int tx = tid & 15, ty = tid >> 4;
    int m0 = blockIdx.y * 128, n0 = blockIdx.x * 64;

    float acc[8][4];
#pragma unroll
    for (int i = 0; i < 8; ++i)
#pragma unroll
        for (int j = 0; j < 4; ++j) acc[i][j] = 0.f;

    int ml0 = tid >> 2;
    int kl = (tid & 3) * 4;

    for (int k0 = 0; k0 < K; k0 += 16) {
#pragma unroll
        for (int half = 0; half < 2; ++half) {
            int ml = ml0 + half * 64;
            float4 v = *(const float4*)(A + (size_t)(m0 + ml) * K + k0 + kl);
            As[kl + 0][ml] = v.x; As[kl + 1][ml] = v.y;
            As[kl + 2][ml] = v.z; As[kl + 3][ml] = v.w;
        }
        {
            int nl = tid >> 2;
            float4 v = make_float4(0.f, 0.f, 0.f, 0.f);
            if (n0 + nl < N) v = *(const float4*)(W + (size_t)(n0 + nl) * K + k0 + kl);
            Ws[kl + 0][nl] = v.x; Ws[kl + 1][nl] = v.y;
            Ws[kl + 2][nl] = v.z; Ws[kl + 3][nl] = v.w;
        }
        __syncthreads();
#pragma unroll
        for (int kk = 0; kk < 16; ++kk) {
            float a[8], w[4];
            *(float4*)(a)     = *(const float4*)&As[kk][ty * 8];
            *(float4*)(a + 4) = *(const float4*)&As[kk][ty * 8 + 4];
            *(float4*)(w)     = *(const float4*)&Ws[kk][tx * 4];
#pragma unroll
            for (int i = 0; i < 8; ++i)
#pragma unroll
                for (int j = 0; j < 4; ++j) acc[i][j] += a[i] * w[j];
        }
        __syncthreads();
    }

#pragma unroll
    for (int i = 0; i < 8; ++i) {
        int m = m0 + ty * 8 + i;
#pragma unroll
        for (int j = 0; j < 4; ++j) {
            int n = n0 + tx * 4 + j;
            if (n < N) {
                float v = acc[i][j];
                if (epi == 1) v += R[(size_t)m * N + n];
                C[(size_t)m * N + n] = v;
            }
        }
    }
}

// ---------------- per-(token,head) prep: B/C rmsnorm+bias, dt/alpha/gamma, dtheta, sumx
__global__ void prep_kernel(const float* __restrict__ A_log,
                            const float* __restrict__ dt_bias,
                            const float* __restrict__ B_bias,
                            const float* __restrict__ C_bias,
                            const float* __restrict__ Bnw,
                            const float* __restrict__ Cnw) {
    const unsigned full = 0xffffffffu;
    int lane = threadIdx.x & 31;
    int unit = blockIdx.x * (blockDim.x >> 5) + (threadIdx.x >> 5);
    if (unit >= NTOK * NH) return;
    int t = unit / NH, h = unit % NH;
    const float* p = g_proj + (size_t)t * PROJ;

    // Bm: rmsnorm(64) * w + bias
    {
        const float* br = p + 2 * DINNER + h * DS;
        float b0 = br[lane], b1 = br[lane + 32];
        float ss = b0 * b0 + b1 * b1;
        for (int o = 16; o; o >>= 1) ss += __shfl_xor_sync(full, ss, o);
        float sc = rsqrtf(ss / 64.f + 1e-5f);
        float* out = g_Bm + (size_t)unit * DS;
        out[lane]      = b0 * sc * Bnw[lane]      + B_bias[h * DS + lane];
        out[lane + 32] = b1 * sc * Bnw[lane + 32] + B_bias[h * DS + lane + 32];
    }
    // Cm
    {
        const float* cr = p + 2 * DINNER + NH * DS + h * DS;
        float c0 = cr[lane], c1 = cr[lane + 32];
        float ss = c0 * c0 + c1 * c1;
        for (int o = 16; o; o >>= 1) ss += __shfl_xor_sync(full, ss, o);
        float sc = rsqrtf(ss / 64.f + 1e-5f);
        float* out = g_Cm + (size_t)unit * DS;
        out[lane]      = c0 * sc * Cnw[lane]      + C_bias[h * DS + lane];
        out[lane + 32] = c1 * sc * Cnw[lane + 32] + C_bias[h * DS + lane + 32];
    }
    // sum of x_ssm over headdim
    {
        const float* xr = p + DINNER + h * HD;
        float s = xr[lane] + xr[lane + 32];
        for (int o = 16; o; o >>= 1) s += __shfl_xor_sync(full, s, o);
        if (lane == 0) g_sumx[unit] = s;
    }
    // dt / alpha / gamma / dtheta
    {
        float raw = p[2 * DINNER + 2 * NH * DS + h] + dt_bias[h];
        float dtv = (raw > 20.f) ? raw : log1pf(expf(raw));
        if (lane == 0) {
            float A = -expf(A_log[h]) * dtv;
            float al = expf(A);
            g_alpha[unit] = al;
            g_gamma[unit] = (al - 1.f) / (A + 1e-6f) * 0.5f + 1.f;
        }
        g_dth[(size_t)unit * 32 + lane] =
            dtv * p[2 * DINNER + 2 * NH * DS + NH + h * 32 + lane];
    }
}

// ---------------- rope: cumsum of dt*theta along s, rotate B and C in place --------
__global__ void rope_kernel() {
    int b = blockIdx.x / NH, h = blockIdx.x % NH;
    int r = threadIdx.x;  // 0..31
    float acc = 0.f;
    for (int s = 0; s < SS; ++s) {
        int t = b * SS + s;
        int unit = t * NH + h;
        acc += g_dth[(size_t)unit * 32 + r];
        float sn, c;
        sincosf(acc, &sn, &c);   // FIXED: sincosf(x, sinptr, cosptr) — sin FIRST
        float2* Bp = (float2*)(g_Bm + (size_t)unit * DS);
        float2 v = Bp[r];
        Bp[r] = make_float2(c * v.x - sn * v.y, sn * v.x + c * v.y);
        float2* Cp = (float2*)(g_Cm + (size_t)unit * DS);
        v = Cp[r];
        Cp[r] = make_float2(c * v.x - sn * v.y, sn * v.x + c * v.y);
    }
}

// ---------------- SSM scan: one CTA per (b,h); warp = 2 p's, lane = 2 n's ----------
__global__ __launch_bounds__(1024)
void scan_kernel() {
    int bh = blockIdx.x;
    int b = bh / NH, h = bh % NH;
    int warp = threadIdx.x >> 5, lane = threadIdx.x & 31;
    int p0 = warp * 2, p1 = p0 + 1;
    int tid = threadIdx.x;

    __shared__ float sB[2][64], sC[2][64], sx[2][64], sal[2];

    float h00 = 0.f, h01 = 0.f, h10 = 0.f, h11 = 0.f;

    // prologue: stage step 0
    {
        int t = b * SS;
        int unit = t * NH + h;
        if (tid < 64)       sB[0][tid]      = g_Bm[(size_t)unit * DS + tid];
        else if (tid < 128) sC[0][tid - 64] = g_Cm[(size_t)unit * DS + tid - 64];
        else if (tid < 192) {
            int p = tid - 128;
            sx[0][p] = g_proj[(size_t)t * PROJ + DINNER + h * HD + p] * g_gamma[unit];
        } else if (tid == 192) sal[0] = g_alpha[unit];
    }
    __syncthreads();

    for (int s = 0; s < SS; ++s) {
        int buf = s & 1;
        // prefetch next step into the other buffer
        if (s + 1 < SS) {
            int t = b * SS + s + 1;
            int unit = t * NH + h;
            int nb = buf ^ 1;
            if (tid < 64)       sB[nb][tid]      = g_Bm[(size_t)unit * DS + tid];
            else if (tid < 128) sC[nb][tid - 64] = g_Cm[(size_t)unit * DS + tid - 64];
            else if (tid < 192) {
                int p = tid - 128;
                sx[nb][p] = g_proj[(size_t)t * PROJ + DINNER + h * HD + p] * g_gamma[unit];
            } else if (tid == 192) sal[nb] = g_alpha[unit];
        }

        float al = sal[buf];
        float Bn0 = sB[buf][lane], Bn1 = sB[buf][lane + 32];
        float Cn0 = sC[buf][lane], Cn1 = sC[buf][lane + 32];
        float x0 = sx[buf][p0], x1 = sx[buf][p1];

        h00 = h00 * al + Bn0 * x0;
        h01 = h01 * al + Bn1 * x0;
        h10 = h10 * al + Bn0 * x1;
        h11 = h11 * al + Bn1 * x1;

        float y0 = h00 * Cn0 + h01 * Cn1;
        float y1 = h10 * Cn0 + h11 * Cn1;
        for (int o = 16; o; o >>= 1) {
            y0 += __shfl_down_sync(0xffffffffu, y0, o);
            y1 += __shfl_down_sync(0xffffffffu, y1, o);
        }
        if (lane == 0) {
            int t = b * SS + s;
            float* yo = g_y + (size_t)t * DINNER + h * HD;
            yo[p0] = y0;
            yo[p1] = y1;
        }
        __syncthreads();
    }
}

// ---------------- gating: y = (y + D*sumx) * silu(z) -------------------------------
__global__ void gate_kernel(const float* __restrict__ Dp) {
    int idx = blockIdx.x * blockDim.x + threadIdx.x;
    if (idx >= NTOK * DINNER) return;
    int t = idx / DINNER, c = idx % DINNER;
    int h = c / HD;
    float z = g_proj[(size_t)t * PROJ + c];
    float y = g_y[idx] + Dp[h] * g_sumx[t * NH + h];
    g_y[idx] = y * (z / (1.f + expf(-z)));
}

// ---------------- mlp activation: g = silu(g) * u -----------------------------------
__global__ void silumul_kernel() {
    int i = blockIdx.x * blockDim.x + threadIdx.x;
    if (i >= NTOK * DMLP) return;
    float g = g_g[i];
    g_g[i] = g / (1.f + expf(-g)) * g_u[i];
}

// ---------------- launch -------------------------------------------------------------
extern "C" void kernel_launch(void* const* d_in, const int* in_sizes, int n_in,
                              void* d_out, int out_size) {
    const float* x         = (const float*)d_in[0];
    const float* norm1_w   = (const float*)d_in[1];
    const float* norm2_w   = (const float*)d_in[2];
    const float* in_proj_w = (const float*)d_in[3];
    const float* out_proj_w= (const float*)d_in[4];
    const float* A_log     = (const float*)d_in[5];
    const float* Dp        = (const float*)d_in[6];
    const float* dt_bias   = (const float*)d_in[7];
    const float* B_bias    = (const float*)d_in[8];
    const float* C_bias    = (const float*)d_in[9];
    const float* Bnorm_w   = (const float*)d_in[10];
    const float* Cnorm_w   = (const float*)d_in[11];
    const float* mlp_gate_w= (const float*)d_in[12];
    const float* mlp_up_w  = (const float*)d_in[13];
    const float* mlp_down_w= (const float*)d_in[14];
    float* out = (float*)d_out;

    // h = rmsnorm(x) -> g_h
    rmsnorm_kernel<<<NTOK, 256>>>(x, 0, 1, norm1_w);

    // proj = h @ in_proj_w^T -> g_proj  [2048 x 6936], K=768
    gemm_nt<<<dim3((PROJ + 63) / 64, NTOK / 128), 256>>>(
        nullptr, 1, in_proj_w, nullptr, 0, nullptr, 2, NTOK, PROJ, DD, 0);

    // per-(t,h) prep
    prep_kernel<<<(NTOK * NH + 3) / 4, 128>>>(A_log, dt_bias, B_bias, C_bias,
                                              Bnorm_w, Cnorm_w);

    // rope (cumsum + rotate in place)
    rope_kernel<<<BB * NH, 32>>>();

    // SSM scan -> g_y
    scan_kernel<<<BB * NH, 1024>>>();

    // gate: y = (y + D*sumx) * silu(z)
    gate_kernel<<<(NTOK * DINNER + 255) / 256, 256>>>(Dp);

    // x2 = x + y @ out_proj_w^T   [2048 x 768], K=1536
    gemm_nt<<<dim3(DD / 64, NTOK / 128), 256>>>(
        nullptr, 3, out_proj_w, x, 0, nullptr, 4, NTOK, DD, DINNER, 1);

    // h2 = rmsnorm(x2)
    rmsnorm_kernel<<<NTOK, 256>>>(nullptr, 4, 5, norm2_w);

    // g = h2 @ gate^T, u = h2 @ up^T  [2048 x 1920], K=768
    gemm_nt<<<dim3(DMLP / 64, NTOK / 128), 256>>>(
        nullptr, 5, mlp_gate_w, nullptr, 0, nullptr, 6, NTOK, DMLP, DD, 0);
    gemm_nt<<<dim3(DMLP / 64, NTOK / 128), 256>>>(
        nullptr, 5, mlp_up_w, nullptr, 0, nullptr, 7, NTOK, DMLP, DD, 0);

    // g = silu(g) * u
    silumul_kernel<<<(NTOK * DMLP + 255) / 256, 256>>>();

    // out = x2 + g @ down^T   [2048 x 768], K=1920
    gemm_nt<<<dim3(DD / 64, NTOK / 128), 256>>>(
        nullptr, 6, mlp_down_w, nullptr, 4, out, 0, NTOK, DD, DMLP, 1);
}

// round 4
// speedup vs baseline: 1.4028x; 1.4028x over previous
#include <cuda_runtime.h>
#include <cuda_bf16.h>
#include <math.h>
#include <stdint.h>

#define BB 2
#define SS 1024
#define DD 768
#define DINNER 1536
#define NH 24
#define HD 64
#define DS 64
#define DMLP 1920
#define PROJ 6936
#define NTOK (BB*SS)

// ---------------- fp32 scratch ----------------
__device__ __align__(16) float g_proj [NTOK*PROJ];
__device__ __align__(16) float g_Bm   [NTOK*NH*DS];
__device__ __align__(16) float g_Cm   [NTOK*NH*DS];
__device__ __align__(16) float g_dth  [NTOK*NH*(DS/2)];
__device__ __align__(16) float g_alpha[NTOK*NH];
__device__ __align__(16) float g_gamma[NTOK*NH];
__device__ __align__(16) float g_sumx [NTOK*NH];
__device__ __align__(16) float g_y    [NTOK*DINNER];
__device__ __align__(16) float g_x2   [NTOK*DD];
__device__ __align__(16) float g_g    [NTOK*DMLP];
__device__ __align__(16) float g_u    [NTOK*DMLP];

// ---------------- bf16 split buffers (hi/lo) ----------------
__device__ __align__(16) __nv_bfloat16 b_h_hi [NTOK*DD],    b_h_lo [NTOK*DD];
__device__ __align__(16) __nv_bfloat16 b_w1_hi[PROJ*DD],    b_w1_lo[PROJ*DD];
__device__ __align__(16) __nv_bfloat16 b_y_hi [NTOK*DINNER],b_y_lo [NTOK*DINNER];
__device__ __align__(16) __nv_bfloat16 b_w2_hi[DD*DINNER],  b_w2_lo[DD*DINNER];
__device__ __align__(16) __nv_bfloat16 b_h2_hi[NTOK*DD],    b_h2_lo[NTOK*DD];
__device__ __align__(16) __nv_bfloat16 b_wg_hi[DMLP*DD],    b_wg_lo[DMLP*DD];
__device__ __align__(16) __nv_bfloat16 b_wu_hi[DMLP*DD],    b_wu_lo[DMLP*DD];
__device__ __align__(16) __nv_bfloat16 b_gg_hi[NTOK*DMLP],  b_gg_lo[NTOK*DMLP];
__device__ __align__(16) __nv_bfloat16 b_wd_hi[DD*DMLP],    b_wd_lo[DD*DMLP];

__device__ __forceinline__ float* resolve(int id) {
    switch (id) {
        case 2: return g_proj;
        case 3: return g_y;
        case 4: return g_x2;
        case 6: return g_g;
        case 7: return g_u;
    }
    return nullptr;
}
__device__ __forceinline__ __nv_bfloat16* resolve_b(int id) {
    switch (id) {
        case 1: return b_h_hi;  case 2: return b_h_lo;
        case 3: return b_w1_hi; case 4: return b_w1_lo;
        case 5: return b_y_hi;  case 6: return b_y_lo;
        case 7: return b_w2_hi; case 8: return b_w2_lo;
        case 9: return b_h2_hi; case 10: return b_h2_lo;
        case 11: return b_wg_hi;case 12: return b_wg_lo;
        case 13: return b_wu_hi;case 14: return b_wu_lo;
        case 15: return b_gg_hi;case 16: return b_gg_lo;
        case 17: return b_wd_hi;case 18: return b_wd_lo;
    }
    return nullptr;
}

__device__ __forceinline__ uint32_t smem_u32(const void* p) {
    uint32_t a;
    asm("{ .reg .u64 t; cvta.to.shared.u64 t, %1; cvt.u32.u64 %0, t; }"
        : "=r"(a) : "l"(p));
    return a;
}
__device__ __forceinline__ void ldsm_x4(uint32_t* r, uint32_t addr) {
    asm volatile("ldmatrix.sync.aligned.m8n8.x4.shared.b16 {%0,%1,%2,%3}, [%4];"
                 : "=r"(r[0]), "=r"(r[1]), "=r"(r[2]), "=r"(r[3]) : "r"(addr));
}
__device__ __forceinline__ void mma16816(float* d, const uint32_t* a,
                                         const uint32_t b0, const uint32_t b1) {
    asm volatile(
        "mma.sync.aligned.m16n8k16.row.col.f32.bf16.bf16.f32 "
        "{%0,%1,%2,%3}, {%4,%5,%6,%7}, {%8,%9}, {%0,%1,%2,%3};"
        : "+f"(d[0]), "+f"(d[1]), "+f"(d[2]), "+f"(d[3])
        : "r"(a[0]), "r"(a[1]), "r"(a[2]), "r"(a[3]), "r"(b0), "r"(b1));
}

// ---------------- HMMA GEMM: C[M,N] = A*W^T via 3x bf16 split (+R) ----------------
// CTA 128(M) x 64(N), BK=32, 256 threads = 8 warps (4x2), warp tile 32x32.
#define PADK 40   // bf16 per smem row (32 data + 8 pad) -> 80B stride
__global__ __launch_bounds__(256)
void gemm_mma(int aHi, int aLo, int wHi, int wLo,
              const float* __restrict__ Rext, int Rid,
              float* __restrict__ Cext, int Cid,
              int M, int N, int K, int epi) {
    const __nv_bfloat16* Ah = resolve_b(aHi);
    const __nv_bfloat16* Al = resolve_b(aLo);
    const __nv_bfloat16* Wh = resolve_b(wHi);
    const __nv_bfloat16* Wl = resolve_b(wLo);
    float* C = Cext ? Cext : resolve(Cid);
    const float* R = epi ? (Rext ? Rext : resolve(Rid)) : nullptr;

    __shared__ __nv_bfloat16 sAh[128 * PADK], sAl[128 * PADK];
    __shared__ __nv_bfloat16 sWh[64 * PADK],  sWl[64 * PADK];

    int tid = threadIdx.x, lane = tid & 31, warp = tid >> 5;
    int wm = (warp >> 1) * 32, wn = (warp & 1) * 32;
    int m0 = blockIdx.y * 128, n0 = blockIdx.x * 64;

    float acc[2][4][4];
#pragma unroll
    for (int t = 0; t < 2; ++t)
#pragma unroll
        for (int j = 0; j < 4; ++j)
#pragma unroll
            for (int q = 0; q < 4; ++q) acc[t][j][q] = 0.f;

    // gmem->smem mapping: 4 threads per 32-elem (64B) row
    int lr = tid >> 2;          // 0..63
    int lc = (tid & 3) * 8;     // bf16 offset within row (16B units of 8 bf16)

    // ldmatrix source addresses (computed once)
    int a_row = (lane & 15), a_colsel = (lane >> 4) * 8;           // A tiles
    int w_row = (lane & 7) + ((lane >> 4) << 3), w_colsel = ((lane >> 3) & 1) * 8;

    for (int k0 = 0; k0 < K; k0 += 32) {
        // A: 128 rows x 32 bf16 (two 64-row halves per thread)
#pragma unroll
        for (int half = 0; half < 2; ++half) {
            int row = lr + half * 64;
            const uint4* srcH = (const uint4*)(Ah + (size_t)(m0 + row) * K + k0 + lc);
            const uint4* srcL = (const uint4*)(Al + (size_t)(m0 + row) * K + k0 + lc);
            *(uint4*)&sAh[row * PADK + lc] = *srcH;
            *(uint4*)&sAl[row * PADK + lc] = *srcL;
        }
        // W: 64 rows x 32 bf16, zero-fill OOB rows
        {
            bool ok = (n0 + lr) < N;
            uint4 z = make_uint4(0, 0, 0, 0);
            uint4 vh = ok ? *(const uint4*)(Wh + (size_t)(n0 + lr) * K + k0 + lc) : z;
            uint4 vl = ok ? *(const uint4*)(Wl + (size_t)(n0 + lr) * K + k0 + lc) : z;
            *(uint4*)&sWh[lr * PADK + lc] = vh;
            *(uint4*)&sWl[lr * PADK + lc] = vl;
        }
        __syncthreads();

        uint32_t ah[2][2][4], al[2][2][4], wh[2][2][4], wl[2][2][4];
#pragma unroll
        for (int t = 0; t < 2; ++t)
#pragma unroll
            for (int s = 0; s < 2; ++s) {
                int row = wm + t * 16 + a_row;
                int col = s * 16 + a_colsel;
                ldsm_x4(ah[t][s], smem_u32(&sAh[row * PADK + col]));
                ldsm_x4(al[t][s], smem_u32(&sAl[row * PADK + col]));
            }
#pragma unroll
        for (int p = 0; p < 2; ++p)
#pragma unroll
            for (int s = 0; s < 2; ++s) {
                int row = wn + p * 16 + w_row;
                int col = s * 16 + w_colsel;
                ldsm_x4(wh[p][s], smem_u32(&sWh[row * PADK + col]));
                ldsm_x4(wl[p][s], smem_u32(&sWl[row * PADK + col]));
            }

#pragma unroll
        for (int t = 0; t < 2; ++t)
#pragma unroll
            for (int j = 0; j < 4; ++j) {
                int p = j >> 1, i2 = (j & 1) * 2;
#pragma unroll
                for (int s = 0; s < 2; ++s) {
                    mma16816(acc[t][j], ah[t][s], wh[p][s][i2], wh[p][s][i2 + 1]);
                    mma16816(acc[t][j], ah[t][s], wl[p][s][i2], wl[p][s][i2 + 1]);
                    mma16816(acc[t][j], al[t][s], wh[p][s][i2], wh[p][s][i2 + 1]);
                }
            }
        __syncthreads();
    }

    // epilogue: C fragment -> gmem (float2 stores)
#pragma unroll
    for (int t = 0; t < 2; ++t) {
        int r0 = m0 + wm + t * 16 + (lane >> 2);
#pragma unroll
        for (int j = 0; j < 4; ++j) {
            int col = n0 + wn + j * 8 + (lane & 3) * 2;
            if (col < N) {
                float2 v0 = make_float2(acc[t][j][0], acc[t][j][1]);
                float2 v1 = make_float2(acc[t][j][2], acc[t][j][3]);
                if (epi) {
                    float2 r;
                    r = *(const float2*)(R + (size_t)r0 * N + col);
                    v0.x += r.x; v0.y += r.y;
                    r = *(const float2*)(R + (size_t)(r0 + 8) * N + col);
                    v1.x += r.x; v1.y += r.y;
                }
                *(float2*)(C + (size_t)r0 * N + col) = v0;
                *(float2*)(C + (size_t)(r0 + 8) * N + col) = v1;
            }
        }
    }
}

// ---------------- weight fp32 -> bf16 hi/lo ----------------
__global__ void cvt_w(const float* __restrict__ src, int hiId, int loId, int n) {
    int i = blockIdx.x * blockDim.x + threadIdx.x;
    if (i >= n) return;
    __nv_bfloat16* hi = resolve_b(hiId);
    __nv_bfloat16* lo = resolve_b(loId);
    float v = src[i];
    __nv_bfloat16 h = __float2bfloat16(v);
    hi[i] = h;
    lo[i] = __float2bfloat16(v - __bfloat162float(h));
}

// ---------------- rmsnorm(768) -> bf16 hi/lo ----------------
__global__ void rmsnorm_b16(const float* __restrict__ src_ext, int src_id,
                            const float* __restrict__ w, int hiId, int loId) {
    const float* src = src_ext ? src_ext : resolve(src_id);
    __nv_bfloat16* hi = resolve_b(hiId);
    __nv_bfloat16* lo = resolve_b(loId);
    int t = blockIdx.x;
    const float* row = src + (size_t)t * DD;
    float s = 0.f;
    for (int i = threadIdx.x; i < DD; i += blockDim.x) { float v = row[i]; s += v * v; }
    __shared__ float sh[8];
    for (int o = 16; o; o >>= 1) s += __shfl_down_sync(0xffffffffu, s, o);
    if ((threadIdx.x & 31) == 0) sh[threadIdx.x >> 5] = s;
    __syncthreads();
    if (threadIdx.x < 8) {
        float v = sh[threadIdx.x];
        for (int o = 4; o; o >>= 1) v += __shfl_down_sync(0xffu, v, o);
        if (threadIdx.x == 0) sh[0] = v;
    }
    __syncthreads();
    float scale = rsqrtf(sh[0] / (float)DD + 1e-5f);
    for (int i = threadIdx.x; i < DD; i += blockDim.x) {
        float v = row[i] * scale * w[i];
        __nv_bfloat16 h = __float2bfloat16(v);
        hi[(size_t)t * DD + i] = h;
        lo[(size_t)t * DD + i] = __float2bfloat16(v - __bfloat162float(h));
    }
}

// ---------------- per-(token,head) prep ----------------
__global__ void prep_kernel(const float* __restrict__ A_log,
                            const float* __restrict__ dt_bias,
                            const float* __restrict__ B_bias,
                            const float* __restrict__ C_bias,
                            const float* __restrict__ Bnw,
                            const float* __restrict__ Cnw) {
    const unsigned full = 0xffffffffu;
    int lane = threadIdx.x & 31;
    int unit = blockIdx.x * (blockDim.x >> 5) + (threadIdx.x >> 5);
    if (unit >= NTOK * NH) return;
    int t = unit / NH, h = unit % NH;
    const float* p = g_proj + (size_t)t * PROJ;
    {
        const float* br = p + 2 * DINNER + h * DS;
        float b0 = br[lane], b1 = br[lane + 32];
        float ss = b0 * b0 + b1 * b1;
        for (int o = 16; o; o >>= 1) ss += __shfl_xor_sync(full, ss, o);
        float sc = rsqrtf(ss / 64.f + 1e-5f);
        float* out = g_Bm + (size_t)unit * DS;
        out[lane]      = b0 * sc * Bnw[lane]      + B_bias[h * DS + lane];
        out[lane + 32] = b1 * sc * Bnw[lane + 32] + B_bias[h * DS + lane + 32];
    }
    {
        const float* cr = p + 2 * DINNER + NH * DS + h * DS;
        float c0 = cr[lane], c1 = cr[lane + 32];
        float ss = c0 * c0 + c1 * c1;
        for (int o = 16; o; o >>= 1) ss += __shfl_xor_sync(full, ss, o);
        float sc = rsqrtf(ss / 64.f + 1e-5f);
        float* out = g_Cm + (size_t)unit * DS;
        out[lane]      = c0 * sc * Cnw[lane]      + C_bias[h * DS + lane];
        out[lane + 32] = c1 * sc * Cnw[lane + 32] + C_bias[h * DS + lane + 32];
    }
    {
        const float* xr = p + DINNER + h * HD;
        float s = xr[lane] + xr[lane + 32];
        for (int o = 16; o; o >>= 1) s += __shfl_xor_sync(full, s, o);
        if (lane == 0) g_sumx[unit] = s;
    }
    {
        float raw = p[2 * DINNER + 2 * NH * DS + h] + dt_bias[h];
        float dtv = (raw > 20.f) ? raw : log1pf(expf(raw));
        if (lane == 0) {
            float A = -expf(A_log[h]) * dtv;
            float al = expf(A);
            g_alpha[unit] = al;
            g_gamma[unit] = (al - 1.f) / (A + 1e-6f) * 0.5f + 1.f;
        }
        g_dth[(size_t)unit * 32 + lane] =
            dtv * p[2 * DINNER + 2 * NH * DS + NH + h * 32 + lane];
    }
}

// ---------------- rope: cumsum + rotate ----------------
__global__ void rope_kernel() {
    int b = blockIdx.x / NH, h = blockIdx.x % NH;
    int r = threadIdx.x;
    float acc = 0.f;
    for (int s = 0; s < SS; ++s) {
        int t = b * SS + s;
        int unit = t * NH + h;
        acc += g_dth[(size_t)unit * 32 + r];
        float sn, c;
        sincosf(acc, &sn, &c);
        float2* Bp = (float2*)(g_Bm + (size_t)unit * DS);
        float2 v = Bp[r];
        Bp[r] = make_float2(c * v.x - sn * v.y, sn * v.x + c * v.y);
        float2* Cp = (float2*)(g_Cm + (size_t)unit * DS);
        v = Cp[r];
        Cp[r] = make_float2(c * v.x - sn * v.y, sn * v.x + c * v.y);
    }
}

// ---------------- SSM scan ----------------
__global__ __launch_bounds__(1024)
void scan_kernel() {
    int bh = blockIdx.x;
    int b = bh / NH, h = bh % NH;
    int warp = threadIdx.x >> 5, lane = threadIdx.x & 31;
    int p0 = warp * 2, p1 = p0 + 1;
    int tid = threadIdx.x;

    __shared__ float sB[2][64], sC[2][64], sx[2][64], sal[2];
    float h00 = 0.f, h01 = 0.f, h10 = 0.f, h11 = 0.f;

    {
        int t = b * SS;
        int unit = t * NH + h;
        if (tid < 64)       sB[0][tid]      = g_Bm[(size_t)unit * DS + tid];
        else if (tid < 128) sC[0][tid - 64] = g_Cm[(size_t)unit * DS + tid - 64];
        else if (tid < 192) {
            int p = tid - 128;
            sx[0][p] = g_proj[(size_t)t * PROJ + DINNER + h * HD + p] * g_gamma[unit];
        } else if (tid == 192) sal[0] = g_alpha[unit];
    }
    __syncthreads();

    for (int s = 0; s < SS; ++s) {
        int buf = s & 1;
        if (s + 1 < SS) {
            int t = b * SS + s + 1;
            int unit = t * NH + h;
            int nb = buf ^ 1;
            if (tid < 64)       sB[nb][tid]      = g_Bm[(size_t)unit * DS + tid];
            else if (tid < 128) sC[nb][tid - 64] = g_Cm[(size_t)unit * DS + tid - 64];
            else if (tid < 192) {
                int p = tid - 128;
                sx[nb][p] = g_proj[(size_t)t * PROJ + DINNER + h * HD + p] * g_gamma[unit];
            } else if (tid == 192) sal[nb] = g_alpha[unit];
        }

        float al = sal[buf];
        float Bn0 = sB[buf][lane], Bn1 = sB[buf][lane + 32];
        float Cn0 = sC[buf][lane], Cn1 = sC[buf][lane + 32];
        float x0 = sx[buf][p0], x1 = sx[buf][p1];

        h00 = h00 * al + Bn0 * x0;
        h01 = h01 * al + Bn1 * x0;
        h10 = h10 * al + Bn0 * x1;
        h11 = h11 * al + Bn1 * x1;

        float y0 = h00 * Cn0 + h01 * Cn1;
        float y1 = h10 * Cn0 + h11 * Cn1;
        for (int o = 16; o; o >>= 1) {
            y0 += __shfl_down_sync(0xffffffffu, y0, o);
            y1 += __shfl_down_sync(0xffffffffu, y1, o);
        }
        if (lane == 0) {
            int t = b * SS + s;
            float* yo = g_y + (size_t)t * DINNER + h * HD;
            yo[p0] = y0;
            yo[p1] = y1;
        }
        __syncthreads();
    }
}

// ---------------- gate: y = (y + D*sumx) * silu(z) -> bf16 hi/lo ----------------
__global__ void gate_b16(const float* __restrict__ Dp) {
    int idx = blockIdx.x * blockDim.x + threadIdx.x;
    if (idx >= NTOK * DINNER) return;
    int t = idx / DINNER, c = idx % DINNER;
    int h = c / HD;
    float z = g_proj[(size_t)t * PROJ + c];
    float y = g_y[idx] + Dp[h] * g_sumx[t * NH + h];
    float v = y * (z / (1.f + expf(-z)));
    __nv_bfloat16 hv = __float2bfloat16(v);
    b_y_hi[idx] = hv;
    b_y_lo[idx] = __float2bfloat16(v - __bfloat162float(hv));
}

// ---------------- mlp: gg = silu(g) * u -> bf16 hi/lo ----------------
__global__ void silumul_b16() {
    int i = blockIdx.x * blockDim.x + threadIdx.x;
    if (i >= NTOK * DMLP) return;
    float g = g_g[i];
    float v = g / (1.f + expf(-g)) * g_u[i];
    __nv_bfloat16 hv = __float2bfloat16(v);
    b_gg_hi[i] = hv;
    b_gg_lo[i] = __float2bfloat16(v - __bfloat162float(hv));
}

// ---------------- launch ----------------
extern "C" void kernel_launch(void* const* d_in, const int* in_sizes, int n_in,
                              void* d_out, int out_size) {
    const float* x         = (const float*)d_in[0];
    const float* norm1_w   = (const float*)d_in[1];
    const float* norm2_w   = (const float*)d_in[2];
    const float* in_proj_w = (const float*)d_in[3];
    const float* out_proj_w= (const float*)d_in[4];
    const float* A_log     = (const float*)d_in[5];
    const float* Dp        = (const float*)d_in[6];
    const float* dt_bias   = (const float*)d_in[7];
    const float* B_bias    = (const float*)d_in[8];
    const float* C_bias    = (const float*)d_in[9];
    const float* Bnorm_w   = (const float*)d_in[10];
    const float* Cnorm_w   = (const float*)d_in[11];
    const float* mlp_gate_w= (const float*)d_in[12];
    const float* mlp_up_w  = (const float*)d_in[13];
    const float* mlp_down_w= (const float*)d_in[14];
    float* out = (float*)d_out;

    // weight splits
    cvt_w<<<(PROJ*DD + 255) / 256, 256>>>(in_proj_w, 3, 4, PROJ * DD);
    cvt_w<<<(DD*DINNER + 255) / 256, 256>>>(out_proj_w, 7, 8, DD * DINNER);
    cvt_w<<<(DMLP*DD + 255) / 256, 256>>>(mlp_gate_w, 11, 12, DMLP * DD);
    cvt_w<<<(DMLP*DD + 255) / 256, 256>>>(mlp_up_w, 13, 14, DMLP * DD);
    cvt_w<<<(DD*DMLP + 255) / 256, 256>>>(mlp_down_w, 17, 18, DD * DMLP);

    // h = rmsnorm(x) -> bf16 split
    rmsnorm_b16<<<NTOK, 256>>>(x, 0, norm1_w, 1, 2);

    // proj = h @ in_proj^T  [2048 x 6936] K=768
    gemm_mma<<<dim3((PROJ + 63) / 64, NTOK / 128), 256>>>(
        1, 2, 3, 4, nullptr, 0, nullptr, 2, NTOK, PROJ, DD, 0);

    prep_kernel<<<(NTOK * NH + 3) / 4, 128>>>(A_log, dt_bias, B_bias, C_bias,
                                              Bnorm_w, Cnorm_w);
    rope_kernel<<<BB * NH, 32>>>();
    scan_kernel<<<BB * NH, 1024>>>();
    gate_b16<<<(NTOK * DINNER + 255) / 256, 256>>>(Dp);

    // x2 = x + y @ out_proj^T  [2048 x 768] K=1536
    gemm_mma<<<dim3(DD / 64, NTOK / 128), 256>>>(
        5, 6, 7, 8, x, 0, nullptr, 4, NTOK, DD, DINNER, 1);

    // h2 = rmsnorm(x2) -> bf16 split
    rmsnorm_b16<<<NTOK, 256>>>(nullptr, 4, norm2_w, 9, 10);

    // g/u = h2 @ {gate,up}^T  [2048 x 1920] K=768
    gemm_mma<<<dim3(DMLP / 64, NTOK / 128), 256>>>(
        9, 10, 11, 12, nullptr, 0, nullptr, 6, NTOK, DMLP, DD, 0);
    gemm_mma<<<dim3(DMLP / 64, NTOK / 128), 256>>>(
        9, 10, 13, 14, nullptr, 0, nullptr, 7, NTOK, DMLP, DD, 0);

    silumul_b16<<<(NTOK * DMLP + 255) / 256, 256>>>();

    // out = x2 + gg @ down^T  [2048 x 768] K=1920
    gemm_mma<<<dim3(DD / 64, NTOK / 128), 256>>>(
        15, 16, 17, 18, nullptr, 4, out, 0, NTOK, DD, DMLP, 1);
}

// round 5
// speedup vs baseline: 2.1572x; 1.5378x over previous
#include <cuda_runtime.h>
#include <cuda_bf16.h>
#include <math.h>
#include <stdint.h>

#define BB 2
#define SS 1024
#define DD 768
#define DINNER 1536
#define NH 24
#define HD 64
#define DS 64
#define DMLP 1920
#define PROJ 6936
#define NTOK (BB*SS)

// ---------------- fp32 scratch ----------------
__device__ __align__(16) float g_proj [NTOK*PROJ];
__device__ __align__(16) float g_Bm   [NTOK*NH*DS];
__device__ __align__(16) float g_Cm   [NTOK*NH*DS];
__device__ __align__(16) float g_dth  [NTOK*NH*(DS/2)];
__device__ __align__(16) float g_alpha[NTOK*NH];
__device__ __align__(16) float g_sumx [NTOK*NH];
__device__ __align__(16) float g_xs   [NTOK*DINNER];
__device__ __align__(16) float g_y    [NTOK*DINNER];
__device__ __align__(16) float g_x2   [NTOK*DD];
__device__ __align__(16) float g_g    [NTOK*DMLP];
__device__ __align__(16) float g_u    [NTOK*DMLP];

// ---------------- bf16 split buffers (hi/lo) ----------------
__device__ __align__(16) __nv_bfloat16 b_h_hi [NTOK*DD],    b_h_lo [NTOK*DD];
__device__ __align__(16) __nv_bfloat16 b_w1_hi[PROJ*DD],    b_w1_lo[PROJ*DD];
__device__ __align__(16) __nv_bfloat16 b_y_hi [NTOK*DINNER],b_y_lo [NTOK*DINNER];
__device__ __align__(16) __nv_bfloat16 b_w2_hi[DD*DINNER],  b_w2_lo[DD*DINNER];
__device__ __align__(16) __nv_bfloat16 b_h2_hi[NTOK*DD],    b_h2_lo[NTOK*DD];
__device__ __align__(16) __nv_bfloat16 b_wg_hi[DMLP*DD],    b_wg_lo[DMLP*DD];
__device__ __align__(16) __nv_bfloat16 b_wu_hi[DMLP*DD],    b_wu_lo[DMLP*DD];
__device__ __align__(16) __nv_bfloat16 b_gg_hi[NTOK*DMLP],  b_gg_lo[NTOK*DMLP];
__device__ __align__(16) __nv_bfloat16 b_wd_hi[DD*DMLP],    b_wd_lo[DD*DMLP];

__device__ __forceinline__ float* resolve(int id) {
    switch (id) {
        case 2: return g_proj;
        case 3: return g_y;
        case 4: return g_x2;
        case 6: return g_g;
        case 7: return g_u;
    }
    return nullptr;
}
__device__ __forceinline__ __nv_bfloat16* resolve_b(int id) {
    switch (id) {
        case 1: return b_h_hi;  case 2: return b_h_lo;
        case 3: return b_w1_hi; case 4: return b_w1_lo;
        case 5: return b_y_hi;  case 6: return b_y_lo;
        case 7: return b_w2_hi; case 8: return b_w2_lo;
        case 9: return b_h2_hi; case 10: return b_h2_lo;
        case 11: return b_wg_hi;case 12: return b_wg_lo;
        case 13: return b_wu_hi;case 14: return b_wu_lo;
        case 15: return b_gg_hi;case 16: return b_gg_lo;
        case 17: return b_wd_hi;case 18: return b_wd_lo;
    }
    return nullptr;
}

__device__ __forceinline__ uint32_t smem_u32(const void* p) {
    uint32_t a;
    asm("{ .reg .u64 t; cvta.to.shared.u64 t, %1; cvt.u32.u64 %0, t; }"
        : "=r"(a) : "l"(p));
    return a;
}
__device__ __forceinline__ void ldsm_x4(uint32_t* r, uint32_t addr) {
    asm volatile("ldmatrix.sync.aligned.m8n8.x4.shared.b16 {%0,%1,%2,%3}, [%4];"
                 : "=r"(r[0]), "=r"(r[1]), "=r"(r[2]), "=r"(r[3]) : "r"(addr));
}
__device__ __forceinline__ void mma16816(float* d, const uint32_t* a,
                                         const uint32_t b0, const uint32_t b1) {
    asm volatile(
        "mma.sync.aligned.m16n8k16.row.col.f32.bf16.bf16.f32 "
        "{%0,%1,%2,%3}, {%4,%5,%6,%7}, {%8,%9}, {%0,%1,%2,%3};"
        : "+f"(d[0]), "+f"(d[1]), "+f"(d[2]), "+f"(d[3])
        : "r"(a[0]), "r"(a[1]), "r"(a[2]), "r"(a[3]), "r"(b0), "r"(b1));
}

// ---------------- HMMA GEMM: C[M,N] = A*W^T via 3x bf16 split (+R) ----------------
#define PADK 40
__global__ __launch_bounds__(256)
void gemm_mma(int aHi, int aLo, int wHi, int wLo,
              const float* __restrict__ Rext, int Rid,
              float* __restrict__ Cext, int Cid,
              int M, int N, int K, int epi) {
    const __nv_bfloat16* Ah = resolve_b(aHi);
    const __nv_bfloat16* Al = resolve_b(aLo);
    const __nv_bfloat16* Wh = resolve_b(wHi);
    const __nv_bfloat16* Wl = resolve_b(wLo);
    float* C = Cext ? Cext : resolve(Cid);
    const float* R = epi ? (Rext ? Rext : resolve(Rid)) : nullptr;

    __shared__ __nv_bfloat16 sAh[128 * PADK], sAl[128 * PADK];
    __shared__ __nv_bfloat16 sWh[64 * PADK],  sWl[64 * PADK];

    int tid = threadIdx.x, lane = tid & 31, warp = tid >> 5;
    int wm = (warp >> 1) * 32, wn = (warp & 1) * 32;
    int m0 = blockIdx.y * 128, n0 = blockIdx.x * 64;

    float acc[2][4][4];
#pragma unroll
    for (int t = 0; t < 2; ++t)
#pragma unroll
        for (int j = 0; j < 4; ++j)
#pragma unroll
            for (int q = 0; q < 4; ++q) acc[t][j][q] = 0.f;

    int lr = tid >> 2;
    int lc = (tid & 3) * 8;

    int a_row = (lane & 15), a_colsel = (lane >> 4) * 8;
    int w_row = (lane & 7) + ((lane >> 4) << 3), w_colsel = ((lane >> 3) & 1) * 8;

    for (int k0 = 0; k0 < K; k0 += 32) {
#pragma unroll
        for (int half = 0; half < 2; ++half) {
            int row = lr + half * 64;
            const uint4* srcH = (const uint4*)(Ah + (size_t)(m0 + row) * K + k0 + lc);
            const uint4* srcL = (const uint4*)(Al + (size_t)(m0 + row) * K + k0 + lc);
            *(uint4*)&sAh[row * PADK + lc] = *srcH;
            *(uint4*)&sAl[row * PADK + lc] = *srcL;
        }
        {
            bool ok = (n0 + lr) < N;
            uint4 z = make_uint4(0, 0, 0, 0);
            uint4 vh = ok ? *(const uint4*)(Wh + (size_t)(n0 + lr) * K + k0 + lc) : z;
            uint4 vl = ok ? *(const uint4*)(Wl + (size_t)(n0 + lr) * K + k0 + lc) : z;
            *(uint4*)&sWh[lr * PADK + lc] = vh;
            *(uint4*)&sWl[lr * PADK + lc] = vl;
        }
        __syncthreads();

        uint32_t ah[2][2][4], al[2][2][4], wh[2][2][4], wl[2][2][4];
#pragma unroll
        for (int t = 0; t < 2; ++t)
#pragma unroll
            for (int s = 0; s < 2; ++s) {
                int row = wm + t * 16 + a_row;
                int col = s * 16 + a_colsel;
                ldsm_x4(ah[t][s], smem_u32(&sAh[row * PADK + col]));
                ldsm_x4(al[t][s], smem_u32(&sAl[row * PADK + col]));
            }
#pragma unroll
        for (int p = 0; p < 2; ++p)
#pragma unroll
            for (int s = 0; s < 2; ++s) {
                int row = wn + p * 16 + w_row;
                int col = s * 16 + w_colsel;
                ldsm_x4(wh[p][s], smem_u32(&sWh[row * PADK + col]));
                ldsm_x4(wl[p][s], smem_u32(&sWl[row * PADK + col]));
            }

#pragma unroll
        for (int t = 0; t < 2; ++t)
#pragma unroll
            for (int j = 0; j < 4; ++j) {
                int p = j >> 1, i2 = (j & 1) * 2;
#pragma unroll
                for (int s = 0; s < 2; ++s) {
                    mma16816(acc[t][j], ah[t][s], wh[p][s][i2], wh[p][s][i2 + 1]);
                    mma16816(acc[t][j], ah[t][s], wl[p][s][i2], wl[p][s][i2 + 1]);
                    mma16816(acc[t][j], al[t][s], wh[p][s][i2], wh[p][s][i2 + 1]);
                }
            }
        __syncthreads();
    }

#pragma unroll
    for (int t = 0; t < 2; ++t) {
        int r0 = m0 + wm + t * 16 + (lane >> 2);
#pragma unroll
        for (int j = 0; j < 4; ++j) {
            int col = n0 + wn + j * 8 + (lane & 3) * 2;
            if (col < N) {
                float2 v0 = make_float2(acc[t][j][0], acc[t][j][1]);
                float2 v1 = make_float2(acc[t][j][2], acc[t][j][3]);
                if (epi) {
                    float2 r;
                    r = *(const float2*)(R + (size_t)r0 * N + col);
                    v0.x += r.x; v0.y += r.y;
                    r = *(const float2*)(R + (size_t)(r0 + 8) * N + col);
                    v1.x += r.x; v1.y += r.y;
                }
                *(float2*)(C + (size_t)r0 * N + col) = v0;
                *(float2*)(C + (size_t)(r0 + 8) * N + col) = v1;
            }
        }
    }
}

// ---------------- fused weight split: all 5 weights in one launch ----------------
__global__ void cvt_all(const float* __restrict__ w1, const float* __restrict__ w2,
                        const float* __restrict__ wg, const float* __restrict__ wu,
                        const float* __restrict__ wd) {
    int i0 = blockIdx.x * blockDim.x + threadIdx.x;
    int stride = gridDim.x * blockDim.x;
#define SPLIT(src, hi, lo, n)                                            \
    for (int i = i0; i < (n); i += stride) {                             \
        float v = src[i];                                                \
        __nv_bfloat16 hh = __float2bfloat16(v);                          \
        hi[i] = hh;                                                      \
        lo[i] = __float2bfloat16(v - __bfloat162float(hh));              \
    }
    SPLIT(w1, b_w1_hi, b_w1_lo, PROJ * DD)
    SPLIT(w2, b_w2_hi, b_w2_lo, DD * DINNER)
    SPLIT(wg, b_wg_hi, b_wg_lo, DMLP * DD)
    SPLIT(wu, b_wu_hi, b_wu_lo, DMLP * DD)
    SPLIT(wd, b_wd_hi, b_wd_lo, DD * DMLP)
#undef SPLIT
}

// ---------------- rmsnorm(768) -> bf16 hi/lo ----------------
__global__ void rmsnorm_b16(const float* __restrict__ src_ext, int src_id,
                            const float* __restrict__ w, int hiId, int loId) {
    const float* src = src_ext ? src_ext : resolve(src_id);
    __nv_bfloat16* hi = resolve_b(hiId);
    __nv_bfloat16* lo = resolve_b(loId);
    int t = blockIdx.x;
    const float* row = src + (size_t)t * DD;
    float s = 0.f;
    for (int i = threadIdx.x; i < DD; i += blockDim.x) { float v = row[i]; s += v * v; }
    __shared__ float sh[8];
    for (int o = 16; o; o >>= 1) s += __shfl_down_sync(0xffffffffu, s, o);
    if ((threadIdx.x & 31) == 0) sh[threadIdx.x >> 5] = s;
    __syncthreads();
    if (threadIdx.x < 8) {
        float v = sh[threadIdx.x];
        for (int o = 4; o; o >>= 1) v += __shfl_down_sync(0xffu, v, o);
        if (threadIdx.x == 0) sh[0] = v;
    }
    __syncthreads();
    float scale = rsqrtf(sh[0] / (float)DD + 1e-5f);
    for (int i = threadIdx.x; i < DD; i += blockDim.x) {
        float v = row[i] * scale * w[i];
        __nv_bfloat16 h = __float2bfloat16(v);
        hi[(size_t)t * DD + i] = h;
        lo[(size_t)t * DD + i] = __float2bfloat16(v - __bfloat162float(h));
    }
}

// ---------------- per-(token,head) prep (also packs x*gamma into g_xs) ----------------
__global__ void prep_kernel(const float* __restrict__ A_log,
                            const float* __restrict__ dt_bias,
                            const float* __restrict__ B_bias,
                            const float* __restrict__ C_bias,
                            const float* __restrict__ Bnw,
                            const float* __restrict__ Cnw) {
    const unsigned full = 0xffffffffu;
    int lane = threadIdx.x & 31;
    int unit = blockIdx.x * (blockDim.x >> 5) + (threadIdx.x >> 5);
    if (unit >= NTOK * NH) return;
    int t = unit / NH, h = unit % NH;
    const float* p = g_proj + (size_t)t * PROJ;
    {
        const float* br = p + 2 * DINNER + h * DS;
        float b0 = br[lane], b1 = br[lane + 32];
        float ss = b0 * b0 + b1 * b1;
        for (int o = 16; o; o >>= 1) ss += __shfl_xor_sync(full, ss, o);
        float sc = rsqrtf(ss / 64.f + 1e-5f);
        float* out = g_Bm + (size_t)unit * DS;
        out[lane]      = b0 * sc * Bnw[lane]      + B_bias[h * DS + lane];
        out[lane + 32] = b1 * sc * Bnw[lane + 32] + B_bias[h * DS + lane + 32];
    }
    {
        const float* cr = p + 2 * DINNER + NH * DS + h * DS;
        float c0 = cr[lane], c1 = cr[lane + 32];
        float ss = c0 * c0 + c1 * c1;
        for (int o = 16; o; o >>= 1) ss += __shfl_xor_sync(full, ss, o);
        float sc = rsqrtf(ss / 64.f + 1e-5f);
        float* out = g_Cm + (size_t)unit * DS;
        out[lane]      = c0 * sc * Cnw[lane]      + C_bias[h * DS + lane];
        out[lane + 32] = c1 * sc * Cnw[lane + 32] + C_bias[h * DS + lane + 32];
    }
    {
        // dt/alpha/gamma computed on every lane (no broadcast needed)
        float raw = p[2 * DINNER + 2 * NH * DS + h] + dt_bias[h];
        float dtv = (raw > 20.f) ? raw : log1pf(expf(raw));
        float A = -expf(A_log[h]) * dtv;
        float al = expf(A);
        float gam = (al - 1.f) / (A + 1e-6f) * 0.5f + 1.f;
        if (lane == 0) g_alpha[unit] = al;
        g_dth[(size_t)unit * 32 + lane] =
            dtv * p[2 * DINNER + 2 * NH * DS + NH + h * 32 + lane];
        // x*gamma packed contiguous per unit; also head-sum of x
        const float* xr = p + DINNER + h * HD;
        float x0 = xr[lane], x1 = xr[lane + 32];
        float* xo = g_xs + (size_t)unit * HD;
        xo[lane]      = x0 * gam;
        xo[lane + 32] = x1 * gam;
        float s = x0 + x1;
        for (int o = 16; o; o >>= 1) s += __shfl_xor_sync(full, s, o);
        if (lane == 0) g_sumx[unit] = s;
    }
}

// ---------------- rope: parallel block-scan over s per (b,h), loop r ----------------
__global__ __launch_bounds__(1024)
void rope_kernel() {
    const unsigned full = 0xffffffffu;
    int bh = blockIdx.x;
    int b = bh / NH, h = bh % NH;
    int s = threadIdx.x;
    int lane = s & 31, warp = s >> 5;
    size_t unit = (size_t)(b * SS + s) * NH + h;
    float2* Bp = (float2*)(g_Bm + unit * DS);
    float2* Cp = (float2*)(g_Cm + unit * DS);
    const float* dthp = g_dth + unit * 32;
    __shared__ float wsum[32];

#pragma unroll 1
    for (int r = 0; r < 32; ++r) {
        float v = dthp[r];
        // inclusive warp scan
#pragma unroll
        for (int o = 1; o < 32; o <<= 1) {
            float n = __shfl_up_sync(full, v, o);
            if (lane >= o) v += n;
        }
        if (lane == 31) wsum[warp] = v;
        __syncthreads();
        if (warp == 0) {
            float w = wsum[lane];
#pragma unroll
            for (int o = 1; o < 32; o <<= 1) {
                float n = __shfl_up_sync(full, w, o);
                if (lane >= o) w += n;
            }
            wsum[lane] = w;
        }
        __syncthreads();
        float ang = v + (warp > 0 ? wsum[warp - 1] : 0.f);
        float sn, c;
        sincosf(ang, &sn, &c);
        float2 bv = Bp[r];
        Bp[r] = make_float2(c * bv.x - sn * bv.y, sn * bv.x + c * bv.y);
        float2 cv = Cp[r];
        Cp[r] = make_float2(c * cv.x - sn * cv.y, sn * cv.x + c * cv.y);
        __syncthreads();
    }
}

// ---------------- SSM scan: warp-independent, no barriers, reg prefetch ----------------
__global__ __launch_bounds__(1024)
void scan_kernel() {
    int bh = blockIdx.x;
    int b = bh / NH, h = bh % NH;
    int warp = threadIdx.x >> 5, lane = threadIdx.x & 31;
    int p0 = warp * 2, p1 = p0 + 1;

    const float* B  = g_Bm + ((size_t)(b * SS) * NH + h) * DS;
    const float* Cc = g_Cm + ((size_t)(b * SS) * NH + h) * DS;
    const float* xs = g_xs + ((size_t)(b * SS) * NH + h) * HD;
    const float* alp = g_alpha + (size_t)(b * SS) * NH + h;
    float* yo = g_y + (size_t)(b * SS) * DINNER + h * HD;
    const int strideU = NH * DS;   // == NH*HD

    float h00 = 0.f, h01 = 0.f, h10 = 0.f, h11 = 0.f;
    float nB0 = B[lane], nB1 = B[lane + 32];
    float nC0 = Cc[lane], nC1 = Cc[lane + 32];
    float nx0 = xs[p0], nx1 = xs[p1];
    float nal = *alp;

    for (int s = 0; s < SS; ++s) {
        float B0 = nB0, B1 = nB1, C0 = nC0, C1 = nC1;
        float x0 = nx0, x1 = nx1, al = nal;
        if (s + 1 < SS) {
            B += strideU; Cc += strideU; xs += strideU; alp += NH;
            nB0 = __ldg(B + lane);  nB1 = __ldg(B + lane + 32);
            nC0 = __ldg(Cc + lane); nC1 = __ldg(Cc + lane + 32);
            nx0 = __ldg(xs + p0);   nx1 = __ldg(xs + p1);
            nal = __ldg(alp);
        }
        h00 = h00 * al + B0 * x0;
        h01 = h01 * al + B1 * x0;
        h10 = h10 * al + B0 * x1;
        h11 = h11 * al + B1 * x1;
        float y0 = h00 * C0 + h01 * C1;
        float y1 = h10 * C0 + h11 * C1;
#pragma unroll
        for (int o = 16; o; o >>= 1) {
            y0 += __shfl_down_sync(0xffffffffu, y0, o);
            y1 += __shfl_down_sync(0xffffffffu, y1, o);
        }
        if (lane == 0) { yo[p0] = y0; yo[p1] = y1; }
        yo += DINNER;
    }
}

// ---------------- gate: y = (y + D*sumx) * silu(z) -> bf16 hi/lo ----------------
__global__ void gate_b16(const float* __restrict__ Dp) {
    int idx = blockIdx.x * blockDim.x + threadIdx.x;
    if (idx >= NTOK * DINNER) return;
    int t = idx / DINNER, c = idx % DINNER;
    int h = c / HD;
    float z = g_proj[(size_t)t * PROJ + c];
    float y = g_y[idx] + Dp[h] * g_sumx[t * NH + h];
    float v = y * (z / (1.f + expf(-z)));
    __nv_bfloat16 hv = __float2bfloat16(v);
    b_y_hi[idx] = hv;
    b_y_lo[idx] = __float2bfloat16(v - __bfloat162float(hv));
}

// ---------------- mlp: gg = silu(g) * u -> bf16 hi/lo ----------------
__global__ void silumul_b16() {
    int i = blockIdx.x * blockDim.x + threadIdx.x;
    if (i >= NTOK * DMLP) return;
    float g = g_g[i];
    float v = g / (1.f + expf(-g)) * g_u[i];
    __nv_bfloat16 hv = __float2bfloat16(v);
    b_gg_hi[i] = hv;
    b_gg_lo[i] = __float2bfloat16(v - __bfloat162float(hv));
}

// ---------------- launch ----------------
extern "C" void kernel_launch(void* const* d_in, const int* in_sizes, int n_in,
                              void* d_out, int out_size) {
    const float* x         = (const float*)d_in[0];
    const float* norm1_w   = (const float*)d_in[1];
    const float* norm2_w   = (const float*)d_in[2];
    const float* in_proj_w = (const float*)d_in[3];
    const float* out_proj_w= (const float*)d_in[4];
    const float* A_log     = (const float*)d_in[5];
    const float* Dp        = (const float*)d_in[6];
    const float* dt_bias   = (const float*)d_in[7];
    const float* B_bias    = (const float*)d_in[8];
    const float* C_bias    = (const float*)d_in[9];
    const float* Bnorm_w   = (const float*)d_in[10];
    const float* Cnorm_w   = (const float*)d_in[11];
    const float* mlp_gate_w= (const float*)d_in[12];
    const float* mlp_up_w  = (const float*)d_in[13];
    const float* mlp_down_w= (const float*)d_in[14];
    float* out = (float*)d_out;

    // all weight splits in one launch
    cvt_all<<<(PROJ * DD + 255) / 256, 256>>>(in_proj_w, out_proj_w,
                                              mlp_gate_w, mlp_up_w, mlp_down_w);

    rmsnorm_b16<<<NTOK, 256>>>(x, 0, norm1_w, 1, 2);

    gemm_mma<<<dim3((PROJ + 63) / 64, NTOK / 128), 256>>>(
        1, 2, 3, 4, nullptr, 0, nullptr, 2, NTOK, PROJ, DD, 0);

    prep_kernel<<<(NTOK * NH + 3) / 4, 128>>>(A_log, dt_bias, B_bias, C_bias,
                                              Bnorm_w, Cnorm_w);
    rope_kernel<<<BB * NH, 1024>>>();
    scan_kernel<<<BB * NH, 1024>>>();
    gate_b16<<<(NTOK * DINNER + 255) / 256, 256>>>(Dp);

    gemm_mma<<<dim3(DD / 64, NTOK / 128), 256>>>(
        5, 6, 7, 8, x, 0, nullptr, 4, NTOK, DD, DINNER, 1);

    rmsnorm_b16<<<NTOK, 256>>>(nullptr, 4, norm2_w, 9, 10);

    gemm_mma<<<dim3(DMLP / 64, NTOK / 128), 256>>>(
        9, 10, 11, 12, nullptr, 0, nullptr, 6, NTOK, DMLP, DD, 0);
    gemm_mma<<<dim3(DMLP / 64, NTOK / 128), 256>>>(
        9, 10, 13, 14, nullptr, 0, nullptr, 7, NTOK, DMLP, DD, 0);

    silumul_b16<<<(NTOK * DMLP + 255) / 256, 256>>>();

    gemm_mma<<<dim3(DD / 64, NTOK / 128), 256>>>(
        15, 16, 17, 18, nullptr, 4, out, 0, NTOK, DD, DMLP, 1);
}